// round 5
// baseline (speedup 1.0000x reference)
#include <cuda_runtime.h>
#include <cuda_bf16.h>
#include <cstddef>

// NetAE batch-1 forward: HBM-bound GEMV chain (~596MB fp32 weights/call).
// Split-K GEMV; previous stage's reduction+bias+relu fused into consumer's
// x-staging prologue. Round 5: D (W_k) and E (W_v) merged into ONE launch
// (independent given e; attention scaling moved into F's prologue), __ldcs
// regression reverted, float4 prologues kept.

#define D_H    2048
#define D_A    256
#define N_EXP  16
#define D_OUT  512

__device__ float g_pA[128 * 2048];
__device__ float g_pB[128 * 2048];
__device__ float g_pC[16 * 32 * 2048];
__device__ float g_pD[16 * 128 * 256];
__device__ float g_pE[16 * 32 * 2048];   // UNSCALED V partials
__device__ float g_pF[128 * 2048];
__device__ float g_pG[256 * 512];
__device__ float g_ekq[16];

__device__ __forceinline__ float4 f4add(float4 a, float4 b) {
    return make_float4(a.x + b.x, a.y + b.y, a.z + b.z, a.w + b.w);
}

// ---------------------------------------------------------------------------
// Shared prologue: build sx[RPS] = x-slice [i0, i0+RPS).
//   MODE 0: sx[r] = xsrc[i0+r]
//   MODE 1: sx[r] = [relu](biasx[bb*NPREV+i0+r] + sum_{s<SPREV} xsrc[(bb*SPREV+s)*NPREV+i0+r])
//   MODE 2: sx[r] = sum_{f<SPREV} ekq[f>>5]*xsrc[f*NPREV+i0+r] + sum_n ekq[n]*bv[n*NPREV+i0+r]
// ---------------------------------------------------------------------------
template<int BLK, int RPS, int MODE, int SPREV, int NPREV, bool RELU_X, bool PREV_PER_B>
__device__ __forceinline__
void stage_x(float* sx, const float* __restrict__ xsrc,
             const float* __restrict__ biasx, const float* __restrict__ bv,
             const float* __restrict__ ekq, int i0, int b)
{
    const int tid = threadIdx.x;
    if constexpr (MODE == 0) {
        for (int r = tid; r < RPS; r += BLK) sx[r] = xsrc[i0 + r];
        __syncthreads();
    } else {
        constexpr int NQ = RPS / 4;
        constexpr int CH = BLK / NQ;
        __shared__ float4 sxp4[BLK];
        const int q = tid % NQ;
        const int c = tid / NQ;
        const int bb = (PREV_PER_B && MODE == 1) ? b : 0;
        const float4* p = reinterpret_cast<const float4*>(
            xsrc + ((size_t)bb * SPREV) * NPREV + i0);
        float4 v = make_float4(0.f, 0.f, 0.f, 0.f);
        #pragma unroll
        for (int s = c; s < SPREV; s += CH) {
            float4 w = p[(size_t)s * (NPREV / 4) + q];
            if constexpr (MODE == 2) {
                const float sc = ekq[s >> 5];
                w.x *= sc; w.y *= sc; w.z *= sc; w.w *= sc;
            }
            v = f4add(v, w);
        }
        sxp4[tid] = v;
        __syncthreads();
        if (tid < NQ) {
            float4 v2;
            if constexpr (MODE == 1) {
                v2 = reinterpret_cast<const float4*>(biasx + (size_t)bb * NPREV + i0)[tid];
            } else {
                v2 = make_float4(0.f, 0.f, 0.f, 0.f);
                #pragma unroll
                for (int n = 0; n < N_EXP; n++) {
                    const float4 bq = reinterpret_cast<const float4*>(
                        bv + (size_t)n * NPREV + i0)[tid];
                    const float e = ekq[n];
                    v2.x += e * bq.x; v2.y += e * bq.y;
                    v2.z += e * bq.z; v2.w += e * bq.w;
                }
            }
            #pragma unroll
            for (int cc = 0; cc < CH; cc++) v2 = f4add(v2, sxp4[tid + cc * NQ]);
            if constexpr (RELU_X) {
                v2.x = fmaxf(v2.x, 0.f); v2.y = fmaxf(v2.y, 0.f);
                v2.z = fmaxf(v2.z, 0.f); v2.w = fmaxf(v2.w, 0.f);
            }
            reinterpret_cast<float4*>(sx)[tid] = v2;
        }
        __syncthreads();
    }
}

// Generic split-K GEMV stage (round-3 main loop: plain unroll, default cache).
template<int BLK, int RPS, int N, int GRP, int MODE, int SPREV, int NPREV,
         bool RELU_X, bool PREV_PER_B>
__global__ __launch_bounds__(BLK)
void gemv_k(const float* __restrict__ W,
            const float* __restrict__ xsrc,
            const float* __restrict__ biasx,
            const float* __restrict__ bv,
            const float* __restrict__ ekq,
            float* __restrict__ partOut)
{
    __shared__ float sx[RPS];
    const int tid   = threadIdx.x;
    const int slice = blockIdx.y;
    const int b     = blockIdx.z;
    const int S     = gridDim.y;
    const int i0    = slice * RPS;
    const int K     = S * RPS;

    stage_x<BLK, RPS, MODE, SPREV, NPREV, RELU_X, PREV_PER_B>(
        sx, xsrc, biasx, bv, ekq, i0, b);

    constexpr int CT  = BLK / GRP;
    constexpr int RPG = RPS / GRP;
    const int g  = tid / CT;
    const int j  = (blockIdx.x * CT + (tid % CT)) * 4;
    const int r0 = g * RPG;

    const float* Wp = W + (size_t)b * K * N + (size_t)(i0 + r0) * N + j;
    float4 acc = make_float4(0.f, 0.f, 0.f, 0.f);
    #pragma unroll 16
    for (int rr = 0; rr < RPG; rr++) {
        const float4 w = *reinterpret_cast<const float4*>(Wp + (size_t)rr * N);
        const float xi = sx[r0 + rr];
        acc.x += xi * w.x;
        acc.y += xi * w.y;
        acc.z += xi * w.z;
        acc.w += xi * w.w;
    }
    *reinterpret_cast<float4*>(
        partOut + ((size_t)((b * S + slice) * GRP + g)) * N + j) = acc;
}

// ---------------------------------------------------------------------------
// Merged D+E stage. grid = (3, 32, 16). Shared fused-e prologue, then:
//   blockIdx.x in {0,1}: E half -> pE[(b*32+slice)*2048 + j]   (unscaled)
//   blockIdx.x == 2    : D      -> pD[((b*32+slice)*4+g)*256 + j]
// ---------------------------------------------------------------------------
__global__ __launch_bounds__(256)
void gemv_DE(const float* __restrict__ Wv, const float* __restrict__ Wk,
             const float* __restrict__ pC, const float* __restrict__ b_exp,
             float* __restrict__ pE, float* __restrict__ pD)
{
    __shared__ float sx[64];
    const int tid   = threadIdx.x;
    const int slice = blockIdx.y;
    const int b     = blockIdx.z;
    const int i0    = slice * 64;

    stage_x<256, 64, 1, 32, 2048, true, true>(sx, pC, b_exp, nullptr, nullptr, i0, b);

    if (blockIdx.x < 2) {                                    // ---- E path ----
        const int j = (blockIdx.x * 256 + tid) * 4;
        const float* Wp = Wv + (size_t)b * 2048 * 2048 + (size_t)i0 * 2048 + j;
        float4 acc = make_float4(0.f, 0.f, 0.f, 0.f);
        #pragma unroll 16
        for (int rr = 0; rr < 64; rr++) {
            const float4 w = *reinterpret_cast<const float4*>(Wp + (size_t)rr * 2048);
            const float xi = sx[rr];
            acc.x += xi * w.x; acc.y += xi * w.y;
            acc.z += xi * w.z; acc.w += xi * w.w;
        }
        *reinterpret_cast<float4*>(pE + ((size_t)(b * 32 + slice)) * 2048 + j) = acc;
    } else {                                                 // ---- D path ----
        const int g  = tid / 64;
        const int j  = (tid % 64) * 4;
        const int r0 = g * 16;
        const float* Wp = Wk + (size_t)b * 2048 * 256 + (size_t)(i0 + r0) * 256 + j;
        float4 acc = make_float4(0.f, 0.f, 0.f, 0.f);
        #pragma unroll 16
        for (int rr = 0; rr < 16; rr++) {
            const float4 w = *reinterpret_cast<const float4*>(Wp + (size_t)rr * 256);
            const float xi = sx[r0 + rr];
            acc.x += xi * w.x; acc.y += xi * w.y;
            acc.z += xi * w.z; acc.w += xi * w.w;
        }
        *reinterpret_cast<float4*>(pD + ((size_t)((b * 32 + slice) * 4 + g)) * 256 + j) = acc;
    }
}

// expkq[n] = (b_k[n] + reduce_{s<128} pD[n]) . (W_q[t][t] + b_q[t])
__global__ __launch_bounds__(256)
void fin_expkq(const float* __restrict__ part,
               const float* __restrict__ b_k,
               const float* __restrict__ W_q,
               const float* __restrict__ b_q,
               const int* __restrict__ task_id,
               float* __restrict__ expkq)
{
    __shared__ float4 red4[256];
    __shared__ float red[64];
    const int n = blockIdx.x;
    const int q = threadIdx.x % 64;
    const int c = threadIdx.x / 64;
    const int t = *task_id;
    const float4* p = reinterpret_cast<const float4*>(part + (size_t)n * 128 * D_A);
    float4 acc = make_float4(0.f, 0.f, 0.f, 0.f);
    #pragma unroll
    for (int s = c; s < 128; s += 4) acc = f4add(acc, p[(size_t)s * 64 + q]);
    red4[threadIdx.x] = acc;
    __syncthreads();
    if (threadIdx.x < 64) {
        float4 k = f4add(f4add(red4[q], red4[q + 64]),
                         f4add(red4[q + 128], red4[q + 192]));
        k = f4add(k, reinterpret_cast<const float4*>(b_k + n * D_A)[q]);
        const float4 wq = reinterpret_cast<const float4*>(
            W_q + ((size_t)t * 10 + t) * D_A)[q];
        const float4 bq = reinterpret_cast<const float4*>(b_q + t * D_A)[q];
        red[q] = k.x * (wq.x + bq.x) + k.y * (wq.y + bq.y)
               + k.z * (wq.z + bq.z) + k.w * (wq.w + bq.w);
    }
    __syncthreads();
    if (threadIdx.x < 32) {
        float v = red[threadIdx.x] + red[threadIdx.x + 32];
        #pragma unroll
        for (int off = 16; off; off >>= 1) v += __shfl_xor_sync(0xFFFFFFFFu, v, off);
        if (threadIdx.x == 0) expkq[n] = v;
    }
}

// out[j] = b_l[j] + reduce_{s<256} pG[s*512 + j]
__global__ __launch_bounds__(256)
void fin_out(const float* __restrict__ part,
             const float* __restrict__ b_l,
             float* __restrict__ out)
{
    __shared__ float4 red4[256];
    const int q = threadIdx.x % 64;
    const int c = threadIdx.x / 64;
    const int jq = blockIdx.x * 64 + q;
    const float4* p = reinterpret_cast<const float4*>(part);
    float4 acc = make_float4(0.f, 0.f, 0.f, 0.f);
    #pragma unroll
    for (int s = c; s < 256; s += 4) acc = f4add(acc, p[(size_t)s * 128 + jq]);
    red4[threadIdx.x] = acc;
    __syncthreads();
    if (threadIdx.x < 64) {
        float4 v = f4add(f4add(red4[q], red4[q + 64]),
                         f4add(red4[q + 128], red4[q + 192]));
        v = f4add(v, reinterpret_cast<const float4*>(b_l)[jq]);
        reinterpret_cast<float4*>(out)[jq] = v;
    }
}

extern "C" void kernel_launch(void* const* d_in, const int* in_sizes, int n_in,
                              void* d_out, int out_size)
{
    const float* x     = (const float*)d_in[0];
    const float* W1    = (const float*)d_in[1];
    const float* b1    = (const float*)d_in[2];
    const float* W2    = (const float*)d_in[3];
    const float* b2    = (const float*)d_in[4];
    const float* W_exp = (const float*)d_in[5];
    const float* b_exp = (const float*)d_in[6];
    const float* W_v   = (const float*)d_in[7];
    const float* b_v   = (const float*)d_in[8];
    const float* W_k   = (const float*)d_in[9];
    const float* b_k   = (const float*)d_in[10];
    const float* W_q   = (const float*)d_in[11];
    const float* b_q   = (const float*)d_in[12];
    const float* W_t   = (const float*)d_in[13];
    const float* b_t   = (const float*)d_in[14];
    const float* W_l   = (const float*)d_in[15];
    const float* b_l   = (const float*)d_in[16];
    const int*   tid   = (const int*)d_in[17];
    float* out = (float*)d_out;

    float *pA, *pB, *pC, *pD, *pE, *pF, *pG, *ekq;
    cudaGetSymbolAddress((void**)&pA, g_pA);
    cudaGetSymbolAddress((void**)&pB, g_pB);
    cudaGetSymbolAddress((void**)&pC, g_pC);
    cudaGetSymbolAddress((void**)&pD, g_pD);
    cudaGetSymbolAddress((void**)&pE, g_pE);
    cudaGetSymbolAddress((void**)&pF, g_pF);
    cudaGetSymbolAddress((void**)&pG, g_pG);
    cudaGetSymbolAddress((void**)&ekq, g_ekq);

    // A: pA = splitK(x @ W1)                         16MB
    gemv_k<256, 16, 2048, 1, 0, 0, 1, false, false>
        <<<dim3(2, 128, 1), 256>>>(W1, x, nullptr, nullptr, nullptr, pA);
    // B: h1 fused; pB = splitK(h1 @ W2)              16MB
    gemv_k<256, 16, 2048, 1, 1, 128, 2048, true, false>
        <<<dim3(2, 128, 1), 256>>>(W2, pA, b1, nullptr, nullptr, pB);
    // C: h2 fused; pC[n] = splitK(h2 @ W_exp[n])     256MB
    gemv_k<256, 64, 2048, 1, 1, 128, 2048, true, false>
        <<<dim3(2, 32, 16), 256>>>(W_exp, pB, b2, nullptr, nullptr, pC);
    // D+E merged: e[n] fused; pD[n] = splitK(e@W_k[n]), pE[n] = splitK(e@W_v[n])  288MB
    gemv_DE<<<dim3(3, 32, 16), 256>>>(W_v, W_k, pC, b_exp, pE, pD);
    // expkq
    fin_expkq<<<16, 256>>>(pD, b_k, W_q, b_q, tid, ekq);
    // F: res fused (per-expert ekq-weighted reduce of pE + ekq.b_v); pF = splitK(res @ W_t)  16MB
    gemv_k<256, 16, 2048, 1, 2, 512, 2048, false, false>
        <<<dim3(2, 128, 1), 256>>>(W_t, pE, nullptr, b_v, ekq, pF);
    // G: t fused; pG = splitK(t @ W_l)               4MB
    gemv_k<256, 16, 512, 2, 1, 128, 2048, true, false>
        <<<dim3(1, 128, 1), 256>>>(W_l, pF, b_t, nullptr, nullptr, pG);
    // out
    fin_out<<<2, 256>>>(pG, b_l, out);
}

// round 6
// speedup vs baseline: 1.0513x; 1.0513x over previous
#include <cuda_runtime.h>
#include <cuda_bf16.h>
#include <cstddef>

// NetAE batch-1 forward: HBM-bound GEMV chain (~596MB fp32 weights/call).
// Round 6: PDL (programmatic dependent launch) across the whole chain.
// Small stages prefetch ALL their weights into registers BEFORE
// cudaGridDependencySynchronize() -> their HBM traffic overlaps the
// producer's drain; launch gaps vanish. Big stages (C, DE) unchanged
// (PF=0, regs=32, occ 82%, already ~76% DRAM).

#define D_H    2048
#define D_A    256
#define N_EXP  16
#define D_OUT  512

__device__ float g_pA[128 * 2048];
__device__ float g_pB[128 * 2048];
__device__ float g_pC[16 * 32 * 2048];
__device__ float g_pD[16 * 128 * 256];
__device__ float g_pE[16 * 32 * 2048];   // UNSCALED V partials
__device__ float g_pF[128 * 2048];
__device__ float g_pG[256 * 512];
__device__ float g_ekq[16];

__device__ __forceinline__ float4 f4add(float4 a, float4 b) {
    return make_float4(a.x + b.x, a.y + b.y, a.z + b.z, a.w + b.w);
}

// ---------------------------------------------------------------------------
// Shared prologue: build sx[RPS] = x-slice [i0, i0+RPS).   (reads producer!)
//   MODE 0: sx[r] = xsrc[i0+r]
//   MODE 1: sx[r] = [relu](biasx[bb*NPREV+i0+r] + sum_{s<SPREV} xsrc[(bb*SPREV+s)*NPREV+i0+r])
//   MODE 2: sx[r] = sum_{f<SPREV} ekq[f>>5]*xsrc[f*NPREV+i0+r] + sum_n ekq[n]*bv[n*NPREV+i0+r]
// ---------------------------------------------------------------------------
template<int BLK, int RPS, int MODE, int SPREV, int NPREV, bool RELU_X, bool PREV_PER_B>
__device__ __forceinline__
void stage_x(float* sx, const float* __restrict__ xsrc,
             const float* __restrict__ biasx, const float* __restrict__ bv,
             const float* __restrict__ ekq, int i0, int b)
{
    const int tid = threadIdx.x;
    if constexpr (MODE == 0) {
        for (int r = tid; r < RPS; r += BLK) sx[r] = xsrc[i0 + r];
        __syncthreads();
    } else {
        constexpr int NQ = RPS / 4;
        constexpr int CH = BLK / NQ;
        __shared__ float4 sxp4[BLK];
        const int q = tid % NQ;
        const int c = tid / NQ;
        const int bb = (PREV_PER_B && MODE == 1) ? b : 0;
        const float4* p = reinterpret_cast<const float4*>(
            xsrc + ((size_t)bb * SPREV) * NPREV + i0);
        float4 v = make_float4(0.f, 0.f, 0.f, 0.f);
        #pragma unroll
        for (int s = c; s < SPREV; s += CH) {
            float4 w = p[(size_t)s * (NPREV / 4) + q];
            if constexpr (MODE == 2) {
                const float sc = ekq[s >> 5];
                w.x *= sc; w.y *= sc; w.z *= sc; w.w *= sc;
            }
            v = f4add(v, w);
        }
        sxp4[tid] = v;
        __syncthreads();
        if (tid < NQ) {
            float4 v2;
            if constexpr (MODE == 1) {
                v2 = reinterpret_cast<const float4*>(biasx + (size_t)bb * NPREV + i0)[tid];
            } else {
                v2 = make_float4(0.f, 0.f, 0.f, 0.f);
                #pragma unroll
                for (int n = 0; n < N_EXP; n++) {
                    const float4 bq = reinterpret_cast<const float4*>(
                        bv + (size_t)n * NPREV + i0)[tid];
                    const float e = ekq[n];
                    v2.x += e * bq.x; v2.y += e * bq.y;
                    v2.z += e * bq.z; v2.w += e * bq.w;
                }
            }
            #pragma unroll
            for (int cc = 0; cc < CH; cc++) v2 = f4add(v2, sxp4[tid + cc * NQ]);
            if constexpr (RELU_X) {
                v2.x = fmaxf(v2.x, 0.f); v2.y = fmaxf(v2.y, 0.f);
                v2.z = fmaxf(v2.z, 0.f); v2.w = fmaxf(v2.w, 0.f);
            }
            reinterpret_cast<float4*>(sx)[tid] = v2;
        }
        __syncthreads();
    }
}

// Generic split-K GEMV stage. PF = rows prefetched into registers before the
// grid-dependency wait (weights are inputs; independent of the producer).
template<int BLK, int RPS, int N, int GRP, int MODE, int SPREV, int NPREV,
         bool RELU_X, bool PREV_PER_B, int PF>
__global__ __launch_bounds__(BLK)
void gemv_k(const float* __restrict__ W,
            const float* __restrict__ xsrc,
            const float* __restrict__ biasx,
            const float* __restrict__ bv,
            const float* __restrict__ ekq,
            float* __restrict__ partOut)
{
    __shared__ float sx[RPS];
    const int tid   = threadIdx.x;
    const int slice = blockIdx.y;
    const int b     = blockIdx.z;
    const int S     = gridDim.y;
    const int i0    = slice * RPS;
    const int K     = S * RPS;

    constexpr int CT  = BLK / GRP;
    constexpr int RPG = RPS / GRP;
    const int g  = tid / CT;
    const int j  = (blockIdx.x * CT + (tid % CT)) * 4;
    const int r0 = g * RPG;
    const float* Wp = W + (size_t)b * K * N + (size_t)(i0 + r0) * N + j;

    float4 wreg[PF > 0 ? PF : 1];
    #pragma unroll
    for (int rr = 0; rr < PF; rr++)
        wreg[rr] = *reinterpret_cast<const float4*>(Wp + (size_t)rr * N);

    cudaGridDependencySynchronize();

    stage_x<BLK, RPS, MODE, SPREV, NPREV, RELU_X, PREV_PER_B>(
        sx, xsrc, biasx, bv, ekq, i0, b);

    float4 acc = make_float4(0.f, 0.f, 0.f, 0.f);
    #pragma unroll
    for (int rr = 0; rr < PF; rr++) {
        const float xi = sx[r0 + rr];
        acc.x += xi * wreg[rr].x; acc.y += xi * wreg[rr].y;
        acc.z += xi * wreg[rr].z; acc.w += xi * wreg[rr].w;
    }
    #pragma unroll 16
    for (int rr = PF; rr < RPG; rr++) {
        const float4 w = *reinterpret_cast<const float4*>(Wp + (size_t)rr * N);
        const float xi = sx[r0 + rr];
        acc.x += xi * w.x; acc.y += xi * w.y;
        acc.z += xi * w.z; acc.w += xi * w.w;
    }
    *reinterpret_cast<float4*>(
        partOut + ((size_t)((b * S + slice) * GRP + g)) * N + j) = acc;
    cudaTriggerProgrammaticLaunchCompletion();
}

// Merged D+E stage. grid = (3, 32, 16). Shared fused-e prologue, then:
//   blockIdx.x in {0,1}: E half -> pE[(b*32+slice)*2048 + j]   (unscaled)
//   blockIdx.x == 2    : D      -> pD[((b*32+slice)*4+g)*256 + j]
__global__ __launch_bounds__(256)
void gemv_DE(const float* __restrict__ Wv, const float* __restrict__ Wk,
             const float* __restrict__ pC, const float* __restrict__ b_exp,
             float* __restrict__ pE, float* __restrict__ pD)
{
    __shared__ float sx[64];
    const int tid   = threadIdx.x;
    const int slice = blockIdx.y;
    const int b     = blockIdx.z;
    const int i0    = slice * 64;

    cudaGridDependencySynchronize();
    stage_x<256, 64, 1, 32, 2048, true, true>(sx, pC, b_exp, nullptr, nullptr, i0, b);

    if (blockIdx.x < 2) {                                    // ---- E path ----
        const int j = (blockIdx.x * 256 + tid) * 4;
        const float* Wp = Wv + (size_t)b * 2048 * 2048 + (size_t)i0 * 2048 + j;
        float4 acc = make_float4(0.f, 0.f, 0.f, 0.f);
        #pragma unroll 16
        for (int rr = 0; rr < 64; rr++) {
            const float4 w = *reinterpret_cast<const float4*>(Wp + (size_t)rr * 2048);
            const float xi = sx[rr];
            acc.x += xi * w.x; acc.y += xi * w.y;
            acc.z += xi * w.z; acc.w += xi * w.w;
        }
        *reinterpret_cast<float4*>(pE + ((size_t)(b * 32 + slice)) * 2048 + j) = acc;
    } else {                                                 // ---- D path ----
        const int g  = tid / 64;
        const int j  = (tid % 64) * 4;
        const int r0 = g * 16;
        const float* Wp = Wk + (size_t)b * 2048 * 256 + (size_t)(i0 + r0) * 256 + j;
        float4 acc = make_float4(0.f, 0.f, 0.f, 0.f);
        #pragma unroll 16
        for (int rr = 0; rr < 16; rr++) {
            const float4 w = *reinterpret_cast<const float4*>(Wp + (size_t)rr * 256);
            const float xi = sx[r0 + rr];
            acc.x += xi * w.x; acc.y += xi * w.y;
            acc.z += xi * w.z; acc.w += xi * w.w;
        }
        *reinterpret_cast<float4*>(pD + ((size_t)((b * 32 + slice) * 4 + g)) * 256 + j) = acc;
    }
    cudaTriggerProgrammaticLaunchCompletion();
}

// expkq[n] = (b_k[n] + reduce_{s<128} pD[n]) . (W_q[t][t] + b_q[t])
__global__ __launch_bounds__(256)
void fin_expkq(const float* __restrict__ part,
               const float* __restrict__ b_k,
               const float* __restrict__ W_q,
               const float* __restrict__ b_q,
               const int* __restrict__ task_id,
               float* __restrict__ expkq)
{
    __shared__ float4 red4[256];
    __shared__ float red[64];
    const int n = blockIdx.x;
    const int q = threadIdx.x % 64;
    const int c = threadIdx.x / 64;
    cudaGridDependencySynchronize();
    const int t = *task_id;
    const float4* p = reinterpret_cast<const float4*>(part + (size_t)n * 128 * D_A);
    float4 acc = make_float4(0.f, 0.f, 0.f, 0.f);
    #pragma unroll
    for (int s = c; s < 128; s += 4) acc = f4add(acc, p[(size_t)s * 64 + q]);
    red4[threadIdx.x] = acc;
    __syncthreads();
    if (threadIdx.x < 64) {
        float4 k = f4add(f4add(red4[q], red4[q + 64]),
                         f4add(red4[q + 128], red4[q + 192]));
        k = f4add(k, reinterpret_cast<const float4*>(b_k + n * D_A)[q]);
        const float4 wq = reinterpret_cast<const float4*>(
            W_q + ((size_t)t * 10 + t) * D_A)[q];
        const float4 bq = reinterpret_cast<const float4*>(b_q + t * D_A)[q];
        red[q] = k.x * (wq.x + bq.x) + k.y * (wq.y + bq.y)
               + k.z * (wq.z + bq.z) + k.w * (wq.w + bq.w);
    }
    __syncthreads();
    if (threadIdx.x < 32) {
        float v = red[threadIdx.x] + red[threadIdx.x + 32];
        #pragma unroll
        for (int off = 16; off; off >>= 1) v += __shfl_xor_sync(0xFFFFFFFFu, v, off);
        if (threadIdx.x == 0) expkq[n] = v;
    }
    cudaTriggerProgrammaticLaunchCompletion();
}

// out[j] = b_l[j] + reduce_{s<256} pG[s*512 + j]
__global__ __launch_bounds__(256)
void fin_out(const float* __restrict__ part,
             const float* __restrict__ b_l,
             float* __restrict__ out)
{
    __shared__ float4 red4[256];
    const int q = threadIdx.x % 64;
    const int c = threadIdx.x / 64;
    const int jq = blockIdx.x * 64 + q;
    cudaGridDependencySynchronize();
    const float4* p = reinterpret_cast<const float4*>(part);
    float4 acc = make_float4(0.f, 0.f, 0.f, 0.f);
    #pragma unroll
    for (int s = c; s < 256; s += 4) acc = f4add(acc, p[(size_t)s * 128 + jq]);
    red4[threadIdx.x] = acc;
    __syncthreads();
    if (threadIdx.x < 64) {
        float4 v = f4add(f4add(red4[q], red4[q + 64]),
                         f4add(red4[q + 128], red4[q + 192]));
        v = f4add(v, reinterpret_cast<const float4*>(b_l)[jq]);
        reinterpret_cast<float4*>(out)[jq] = v;
    }
    cudaTriggerProgrammaticLaunchCompletion();
}

// ---------------------------------------------------------------------------
template<typename K, typename... A>
static inline void launch_pdl(K kern, dim3 g, dim3 b, A... args)
{
    cudaLaunchConfig_t cfg = {};
    cfg.gridDim = g;
    cfg.blockDim = b;
    cfg.stream = 0;
    cudaLaunchAttribute at[1];
    at[0].id = cudaLaunchAttributeProgrammaticStreamSerialization;
    at[0].val.programmaticStreamSerializationAllowed = 1;
    cfg.attrs = at;
    cfg.numAttrs = 1;
    cudaLaunchKernelEx(&cfg, kern, args...);
}

extern "C" void kernel_launch(void* const* d_in, const int* in_sizes, int n_in,
                              void* d_out, int out_size)
{
    const float* x     = (const float*)d_in[0];
    const float* W1    = (const float*)d_in[1];
    const float* b1    = (const float*)d_in[2];
    const float* W2    = (const float*)d_in[3];
    const float* b2    = (const float*)d_in[4];
    const float* W_exp = (const float*)d_in[5];
    const float* b_exp = (const float*)d_in[6];
    const float* W_v   = (const float*)d_in[7];
    const float* b_v   = (const float*)d_in[8];
    const float* W_k   = (const float*)d_in[9];
    const float* b_k   = (const float*)d_in[10];
    const float* W_q   = (const float*)d_in[11];
    const float* b_q   = (const float*)d_in[12];
    const float* W_t   = (const float*)d_in[13];
    const float* b_t   = (const float*)d_in[14];
    const float* W_l   = (const float*)d_in[15];
    const float* b_l   = (const float*)d_in[16];
    const int*   tid   = (const int*)d_in[17];
    float* out = (float*)d_out;

    float *pA, *pB, *pC, *pD, *pE, *pF, *pG, *ekq;
    cudaGetSymbolAddress((void**)&pA, g_pA);
    cudaGetSymbolAddress((void**)&pB, g_pB);
    cudaGetSymbolAddress((void**)&pC, g_pC);
    cudaGetSymbolAddress((void**)&pD, g_pD);
    cudaGetSymbolAddress((void**)&pE, g_pE);
    cudaGetSymbolAddress((void**)&pF, g_pF);
    cudaGetSymbolAddress((void**)&pG, g_pG);
    cudaGetSymbolAddress((void**)&ekq, g_ekq);

    // A: pA = splitK(x @ W1)            16MB, full register prefetch
    launch_pdl(gemv_k<256, 16, 2048, 1, 0, 0, 1, false, false, 16>,
               dim3(2, 128, 1), dim3(256), W1, x, (const float*)nullptr,
               (const float*)nullptr, (const float*)nullptr, pA);
    // B: h1 fused; pB = splitK(h1 @ W2)  16MB, full prefetch overlaps A
    launch_pdl(gemv_k<256, 16, 2048, 1, 1, 128, 2048, true, false, 16>,
               dim3(2, 128, 1), dim3(256), W2, pA, b1,
               (const float*)nullptr, (const float*)nullptr, pB);
    // C: h2 fused; pC[n] = splitK(h2 @ W_exp[n])   256MB, streaming (PF=0)
    launch_pdl(gemv_k<256, 64, 2048, 1, 1, 128, 2048, true, false, 0>,
               dim3(2, 32, 16), dim3(256), W_exp, pB, b2,
               (const float*)nullptr, (const float*)nullptr, pC);
    // D+E merged                                    288MB
    launch_pdl(gemv_DE, dim3(3, 32, 16), dim3(256), W_v, W_k, pC, b_exp, pE, pD);
    // expkq
    launch_pdl(fin_expkq, dim3(16), dim3(256), pD, b_k, W_q, b_q, tid, ekq);
    // F: res fused; pF = splitK(res @ W_t)  16MB, full prefetch overlaps ekq+DE drain
    launch_pdl(gemv_k<256, 16, 2048, 1, 2, 512, 2048, false, false, 16>,
               dim3(2, 128, 1), dim3(256), W_t, pE, (const float*)nullptr,
               b_v, (const float*)ekq, pF);
    // G: t fused; pG = splitK(t @ W_l)      4MB, full prefetch overlaps F
    launch_pdl(gemv_k<256, 16, 512, 2, 1, 128, 2048, true, false, 8>,
               dim3(1, 128, 1), dim3(256), W_l, pF, b_t,
               (const float*)nullptr, (const float*)nullptr, pG);
    // out
    launch_pdl(fin_out, dim3(2), dim3(256), pG, b_l, out);
}

// round 8
// speedup vs baseline: 1.0663x; 1.0142x over previous
#include <cuda_runtime.h>
#include <cuda_bf16.h>
#include <cstddef>

// NetAE batch-1 forward: HBM-bound GEMV chain (~596MB fp32 weights/call).
// Round 8 (= round 7 theory, compile fix): uniform 1024-block DE stage —
// D (W_k) folded INTO the E blocks (288KB/block, single co-resident wave)
// instead of 512 extra blocks (1.48 waves -> 77% DRAM). PDL + register
// weight prefetch kept everywhere.

#define D_H    2048
#define D_A    256
#define N_EXP  16
#define D_OUT  512

__device__ float g_pA[128 * 2048];
__device__ float g_pB[128 * 2048];
__device__ float g_pC[16 * 32 * 2048];
__device__ float g_pD[16 * 256 * 256];   // 8 row-groups x 32 slices deep
__device__ float g_pE[16 * 32 * 2048];   // UNSCALED V partials
__device__ float g_pF[128 * 2048];
__device__ float g_pG[256 * 512];
__device__ float g_ekq[16];

__device__ __forceinline__ float4 f4add(float4 a, float4 b) {
    return make_float4(a.x + b.x, a.y + b.y, a.z + b.z, a.w + b.w);
}

// ---------------------------------------------------------------------------
// Shared prologue: build sx[RPS] = x-slice [i0, i0+RPS).
//   MODE 0: sx[r] = xsrc[i0+r]
//   MODE 1: sx[r] = [relu](biasx[bb*NPREV+i0+r] + sum_{s<SPREV} xsrc[(bb*SPREV+s)*NPREV+i0+r])
//   MODE 2: sx[r] = sum_{f<SPREV} ekq[f>>5]*xsrc[f*NPREV+i0+r] + sum_n ekq[n]*bv[n*NPREV+i0+r]
// ---------------------------------------------------------------------------
template<int BLK, int RPS, int MODE, int SPREV, int NPREV, bool RELU_X, bool PREV_PER_B>
__device__ __forceinline__
void stage_x(float* sx, const float* __restrict__ xsrc,
             const float* __restrict__ biasx, const float* __restrict__ bv,
             const float* __restrict__ ekq, int i0, int b)
{
    const int tid = threadIdx.x;
    if constexpr (MODE == 0) {
        for (int r = tid; r < RPS; r += BLK) sx[r] = xsrc[i0 + r];
        __syncthreads();
    } else {
        constexpr int NQ = RPS / 4;
        constexpr int CH = BLK / NQ;
        __shared__ float4 sxp4[BLK];
        const int q = tid % NQ;
        const int c = tid / NQ;
        const int bb = (PREV_PER_B && MODE == 1) ? b : 0;
        const float4* p = reinterpret_cast<const float4*>(
            xsrc + ((size_t)bb * SPREV) * NPREV + i0);
        float4 v = make_float4(0.f, 0.f, 0.f, 0.f);
        #pragma unroll
        for (int s = c; s < SPREV; s += CH) {
            float4 w = p[(size_t)s * (NPREV / 4) + q];
            if constexpr (MODE == 2) {
                const float sc = ekq[s >> 5];
                w.x *= sc; w.y *= sc; w.z *= sc; w.w *= sc;
            }
            v = f4add(v, w);
        }
        sxp4[tid] = v;
        __syncthreads();
        if (tid < NQ) {
            float4 v2;
            if constexpr (MODE == 1) {
                v2 = reinterpret_cast<const float4*>(biasx + (size_t)bb * NPREV + i0)[tid];
            } else {
                v2 = make_float4(0.f, 0.f, 0.f, 0.f);
                #pragma unroll
                for (int n = 0; n < N_EXP; n++) {
                    const float4 bq = reinterpret_cast<const float4*>(
                        bv + (size_t)n * NPREV + i0)[tid];
                    const float e = ekq[n];
                    v2.x += e * bq.x; v2.y += e * bq.y;
                    v2.z += e * bq.z; v2.w += e * bq.w;
                }
            }
            #pragma unroll
            for (int cc = 0; cc < CH; cc++) v2 = f4add(v2, sxp4[tid + cc * NQ]);
            if constexpr (RELU_X) {
                v2.x = fmaxf(v2.x, 0.f); v2.y = fmaxf(v2.y, 0.f);
                v2.z = fmaxf(v2.z, 0.f); v2.w = fmaxf(v2.w, 0.f);
            }
            reinterpret_cast<float4*>(sx)[tid] = v2;
        }
        __syncthreads();
    }
}

// Generic split-K GEMV stage. PF = rows prefetched into regs before the wait.
template<int BLK, int RPS, int N, int GRP, int MODE, int SPREV, int NPREV,
         bool RELU_X, bool PREV_PER_B, int PF>
__global__ __launch_bounds__(BLK)
void gemv_k(const float* __restrict__ W,
            const float* __restrict__ xsrc,
            const float* __restrict__ biasx,
            const float* __restrict__ bv,
            const float* __restrict__ ekq,
            float* __restrict__ partOut)
{
    __shared__ float sx[RPS];
    const int tid   = threadIdx.x;
    const int slice = blockIdx.y;
    const int b     = blockIdx.z;
    const int S     = gridDim.y;
    const int i0    = slice * RPS;
    const int K     = S * RPS;

    constexpr int CT  = BLK / GRP;
    constexpr int RPG = RPS / GRP;
    const int g  = tid / CT;
    const int j  = (blockIdx.x * CT + (tid % CT)) * 4;
    const int r0 = g * RPG;
    const float* Wp = W + (size_t)b * K * N + (size_t)(i0 + r0) * N + j;

    float4 wreg[PF > 0 ? PF : 1];
    #pragma unroll
    for (int rr = 0; rr < PF; rr++)
        wreg[rr] = *reinterpret_cast<const float4*>(Wp + (size_t)rr * N);

    cudaGridDependencySynchronize();

    stage_x<BLK, RPS, MODE, SPREV, NPREV, RELU_X, PREV_PER_B>(
        sx, xsrc, biasx, bv, ekq, i0, b);

    float4 acc = make_float4(0.f, 0.f, 0.f, 0.f);
    #pragma unroll
    for (int rr = 0; rr < PF; rr++) {
        const float xi = sx[r0 + rr];
        acc.x += xi * wreg[rr].x; acc.y += xi * wreg[rr].y;
        acc.z += xi * wreg[rr].z; acc.w += xi * wreg[rr].w;
    }
    #pragma unroll 16
    for (int rr = PF; rr < RPG; rr++) {
        const float4 w = *reinterpret_cast<const float4*>(Wp + (size_t)rr * N);
        const float xi = sx[r0 + rr];
        acc.x += xi * w.x; acc.y += xi * w.y;
        acc.z += xi * w.z; acc.w += xi * w.w;
    }
    *reinterpret_cast<float4*>(
        partOut + ((size_t)((b * S + slice) * GRP + g)) * N + j) = acc;
    cudaTriggerProgrammaticLaunchCompletion();
}

// ---------------------------------------------------------------------------
// Merged D+E stage, UNIFORM blocks. grid = (2, 32, 16) = 1024 blocks.
// Each block: shared fused-e prologue (64-row slice), then
//   E tile: 64 rows x 1024 V-cols  -> pE[(b*32+slice)*2048 + xp*1024 + ...]
//   D tile: 64 rows x 128 K-cols   -> pD[((b*32+slice)*8+g)*256 + xp*128 + ...]
// 288KB/block, single co-resident wave -> no wave quantization.
// ---------------------------------------------------------------------------
__global__ __launch_bounds__(256)
void gemv_DE(const float* __restrict__ Wv, const float* __restrict__ Wk,
             const float* __restrict__ pC, const float* __restrict__ b_exp,
             float* __restrict__ pE, float* __restrict__ pD)
{
    __shared__ float sx[64];
    const int tid   = threadIdx.x;
    const int xp    = blockIdx.x;
    const int slice = blockIdx.y;
    const int b     = blockIdx.z;
    const int i0    = slice * 64;

    cudaGridDependencySynchronize();
    stage_x<256, 64, 1, 32, 2048, true, true>(sx, pC, b_exp, nullptr, nullptr, i0, b);

    // ---- E tile ----
    {
        const int j = (xp * 256 + tid) * 4;
        const float* Wp = Wv + (size_t)b * 2048 * 2048 + (size_t)i0 * 2048 + j;
        float4 acc = make_float4(0.f, 0.f, 0.f, 0.f);
        #pragma unroll 16
        for (int rr = 0; rr < 64; rr++) {
            const float4 w = *reinterpret_cast<const float4*>(Wp + (size_t)rr * 2048);
            const float xi = sx[rr];
            acc.x += xi * w.x; acc.y += xi * w.y;
            acc.z += xi * w.z; acc.w += xi * w.w;
        }
        *reinterpret_cast<float4*>(pE + ((size_t)(b * 32 + slice)) * 2048 + j) = acc;
    }
    // ---- D tile ----
    {
        const int g  = tid / 32;            // 8 row groups of 8 rows
        const int jd = xp * 128 + (tid % 32) * 4;
        const int r0 = g * 8;
        const float* Wp = Wk + (size_t)b * 2048 * 256 + (size_t)(i0 + r0) * 256 + jd;
        float4 acc = make_float4(0.f, 0.f, 0.f, 0.f);
        #pragma unroll
        for (int rr = 0; rr < 8; rr++) {
            const float4 w = *reinterpret_cast<const float4*>(Wp + (size_t)rr * 256);
            const float xi = sx[r0 + rr];
            acc.x += xi * w.x; acc.y += xi * w.y;
            acc.z += xi * w.z; acc.w += xi * w.w;
        }
        *reinterpret_cast<float4*>(
            pD + ((size_t)((b * 32 + slice) * 8 + g)) * 256 + jd) = acc;
    }
    cudaTriggerProgrammaticLaunchCompletion();
}

// expkq[n] = (b_k[n] + reduce_{s<256} pD[n]) . (W_q[t][t] + b_q[t])
__global__ __launch_bounds__(256)
void fin_expkq(const float* __restrict__ part,
               const float* __restrict__ b_k,
               const float* __restrict__ W_q,
               const float* __restrict__ b_q,
               const int* __restrict__ task_id,
               float* __restrict__ expkq)
{
    __shared__ float4 red4[256];
    __shared__ float red[64];
    const int n = blockIdx.x;
    const int q = threadIdx.x % 64;
    const int c = threadIdx.x / 64;
    cudaGridDependencySynchronize();
    const int t = *task_id;
    const float4* p = reinterpret_cast<const float4*>(part + (size_t)n * 256 * D_A);
    float4 acc = make_float4(0.f, 0.f, 0.f, 0.f);
    #pragma unroll
    for (int s = c; s < 256; s += 4) acc = f4add(acc, p[(size_t)s * 64 + q]);
    red4[threadIdx.x] = acc;
    __syncthreads();
    if (threadIdx.x < 64) {
        float4 k = f4add(f4add(red4[q], red4[q + 64]),
                         f4add(red4[q + 128], red4[q + 192]));
        k = f4add(k, reinterpret_cast<const float4*>(b_k + n * D_A)[q]);
        const float4 wq = reinterpret_cast<const float4*>(
            W_q + ((size_t)t * 10 + t) * D_A)[q];
        const float4 bq = reinterpret_cast<const float4*>(b_q + t * D_A)[q];
        red[q] = k.x * (wq.x + bq.x) + k.y * (wq.y + bq.y)
               + k.z * (wq.z + bq.z) + k.w * (wq.w + bq.w);
    }
    __syncthreads();
    if (threadIdx.x < 32) {
        float v = red[threadIdx.x] + red[threadIdx.x + 32];
        #pragma unroll
        for (int off = 16; off; off >>= 1) v += __shfl_xor_sync(0xFFFFFFFFu, v, off);
        if (threadIdx.x == 0) expkq[n] = v;
    }
    cudaTriggerProgrammaticLaunchCompletion();
}

// out[j] = b_l[j] + reduce_{s<256} pG[s*512 + j]
__global__ __launch_bounds__(256)
void fin_out(const float* __restrict__ part,
             const float* __restrict__ b_l,
             float* __restrict__ out)
{
    __shared__ float4 red4[256];
    const int q = threadIdx.x % 64;
    const int c = threadIdx.x / 64;
    const int jq = blockIdx.x * 64 + q;
    cudaGridDependencySynchronize();
    const float4* p = reinterpret_cast<const float4*>(part);
    float4 acc = make_float4(0.f, 0.f, 0.f, 0.f);
    #pragma unroll
    for (int s = c; s < 256; s += 4) acc = f4add(acc, p[(size_t)s * 128 + jq]);
    red4[threadIdx.x] = acc;
    __syncthreads();
    if (threadIdx.x < 64) {
        float4 v = f4add(f4add(red4[q], red4[q + 64]),
                         f4add(red4[q + 128], red4[q + 192]));
        v = f4add(v, reinterpret_cast<const float4*>(b_l)[jq]);
        reinterpret_cast<float4*>(out)[jq] = v;
    }
    cudaTriggerProgrammaticLaunchCompletion();
}

// ---------------------------------------------------------------------------
template<typename K, typename... A>
static inline void launch_pdl(K kern, dim3 g, dim3 b, A... args)
{
    cudaLaunchConfig_t cfg = {};
    cfg.gridDim = g;
    cfg.blockDim = b;
    cfg.stream = 0;
    cudaLaunchAttribute at[1];
    at[0].id = cudaLaunchAttributeProgrammaticStreamSerialization;
    at[0].val.programmaticStreamSerializationAllowed = 1;
    cfg.attrs = at;
    cfg.numAttrs = 1;
    cudaLaunchKernelEx(&cfg, kern, args...);
}

extern "C" void kernel_launch(void* const* d_in, const int* in_sizes, int n_in,
                              void* d_out, int out_size)
{
    const float* x     = (const float*)d_in[0];
    const float* W1    = (const float*)d_in[1];
    const float* b1    = (const float*)d_in[2];
    const float* W2    = (const float*)d_in[3];
    const float* b2    = (const float*)d_in[4];
    const float* W_exp = (const float*)d_in[5];
    const float* b_exp = (const float*)d_in[6];
    const float* W_v   = (const float*)d_in[7];
    const float* b_v   = (const float*)d_in[8];
    const float* W_k   = (const float*)d_in[9];
    const float* b_k   = (const float*)d_in[10];
    const float* W_q   = (const float*)d_in[11];
    const float* b_q   = (const float*)d_in[12];
    const float* W_t   = (const float*)d_in[13];
    const float* b_t   = (const float*)d_in[14];
    const float* W_l   = (const float*)d_in[15];
    const float* b_l   = (const float*)d_in[16];
    const int*   tid   = (const int*)d_in[17];
    float* out = (float*)d_out;

    float *pA, *pB, *pC, *pD, *pE, *pF, *pG, *ekq;
    cudaGetSymbolAddress((void**)&pA, g_pA);
    cudaGetSymbolAddress((void**)&pB, g_pB);
    cudaGetSymbolAddress((void**)&pC, g_pC);
    cudaGetSymbolAddress((void**)&pD, g_pD);
    cudaGetSymbolAddress((void**)&pE, g_pE);
    cudaGetSymbolAddress((void**)&pF, g_pF);
    cudaGetSymbolAddress((void**)&pG, g_pG);
    cudaGetSymbolAddress((void**)&ekq, g_ekq);

    // A: pA = splitK(x @ W1)            16MB, full register prefetch
    launch_pdl(gemv_k<256, 16, 2048, 1, 0, 0, 1, false, false, 16>,
               dim3(2, 128, 1), dim3(256), W1, x, (const float*)nullptr,
               (const float*)nullptr, (const float*)nullptr, pA);
    // B: h1 fused; pB = splitK(h1 @ W2)  16MB, full prefetch overlaps A
    launch_pdl(gemv_k<256, 16, 2048, 1, 1, 128, 2048, true, false, 16>,
               dim3(2, 128, 1), dim3(256), W2, pA, b1,
               (const float*)nullptr, (const float*)nullptr, pB);
    // C: h2 fused; pC[n] = splitK(h2 @ W_exp[n])   256MB, 1024 blocks
    launch_pdl(gemv_k<256, 64, 2048, 1, 1, 128, 2048, true, false, 0>,
               dim3(2, 32, 16), dim3(256), W_exp, pB, b2,
               (const float*)nullptr, (const float*)nullptr, pC);
    // D+E merged, uniform 1024 blocks                288MB
    launch_pdl(gemv_DE, dim3(2, 32, 16), dim3(256), W_v, W_k, pC, b_exp, pE, pD);
    // expkq
    launch_pdl(fin_expkq, dim3(16), dim3(256), pD, b_k, W_q, b_q, tid, ekq);
    // F: res fused; pF = splitK(res @ W_t)  16MB, full prefetch
    launch_pdl(gemv_k<256, 16, 2048, 1, 2, 512, 2048, false, false, 16>,
               dim3(2, 128, 1), dim3(256), W_t, pE, (const float*)nullptr,
               b_v, (const float*)ekq, pF);
    // G: t fused; pG = splitK(t @ W_l)      4MB, full prefetch
    launch_pdl(gemv_k<256, 16, 512, 2, 1, 128, 2048, true, false, 8>,
               dim3(1, 128, 1), dim3(256), W_l, pF, b_t,
               (const float*)nullptr, (const float*)nullptr, pG);
    // out
    launch_pdl(fin_out, dim3(2), dim3(256), pG, b_l, out);
}